// round 6
// baseline (speedup 1.0000x reference)
#include <cuda_runtime.h>
#include <cstdint>

#define B_   512
#define L_   1024
#define K_   8
#define NR_  512
#define S_   20
#define EXT_ 26
#define SQN  6
#define NTAY 8            // validated: rel_err 1.09e-7
#define NTHR 416          // 13 warps: 8 producers + 5 consumers
#define BPB  2            // batch rows per block
#define ROWW (K_ * EXT_)  // 208
#define RTN  (EXT_ * ROWW)// 5408 floats per RT buffer
#define MSZ  (S_ * S_)    // 400

__device__ __align__(16) float g_Q[K_ * MSZ];

__device__ __forceinline__ float softplus_f(float x) {
    return fmaxf(x, 0.0f) + log1pf(expf(-fabsf(x)));
}

// ---------------------------------------------------------------------------
// Kernel A: build Q[k]
// ---------------------------------------------------------------------------
__global__ void qprep_kernel(const float* __restrict__ exch,
                             const float* __restrict__ freq) {
    const int k = blockIdx.x;
    const int i = threadIdx.y;
    const int j = threadIdx.x;

    __shared__ float Rs[S_][S_ + 1];
    __shared__ float diag[S_];
    __shared__ float fr[S_];

    if (i == 0) fr[j] = freq[j];

    float e1 = exch[(k * S_ + i) * S_ + j];
    float e2 = exch[(k * S_ + j) * S_ + i];
    float r = softplus_f(0.5f * (e1 + e2));
    if (i == j) r = 0.0f;
    __syncthreads();

    float q = r * fr[j];
    Rs[i][j] = q;
    __syncthreads();

    if (j == 0) {
        float d = 0.0f;
        #pragma unroll
        for (int t = 0; t < S_; t++) d += Rs[i][t];
        diag[i] = d;
    }
    __syncthreads();

    float mue = 0.0f;
    #pragma unroll
    for (int t = 0; t < S_; t++) mue += fr[t] * diag[t];
    mue = fmaxf(mue, 1e-16f);

    float val = q - (i == j ? diag[i] : 0.0f);
    g_Q[(k * S_ + i) * S_ + j] = val / mue;
}

// ---------------------------------------------------------------------------
// expm for matrix k into RT's variable region. Warp-collective (v4 scheme).
// ---------------------------------------------------------------------------
__device__ __forceinline__ void expm_into_rt(
        float* __restrict__ RT, float* __restrict__ Arm, float* __restrict__ Tc,
        int k, int lane, float scale) {
    const bool act = (lane < 25);
    const int  a   = lane / 5;
    const int  bb  = lane - a * 5;

    float P[4][4];

    if (act) {
        float4 arow[4];
        #pragma unroll
        for (int r4 = 0; r4 < 4; r4++) {
            float4 q = *(const float4*)(g_Q + (k * S_ + 4 * a + r4) * S_ + 4 * bb);
            arow[r4] = make_float4(q.x * scale, q.y * scale, q.z * scale, q.w * scale);
            *(float4*)(Arm + (4 * a + r4) * S_ + 4 * bb) = arow[r4];
        }
        #pragma unroll
        for (int c = 0; c < 4; c++) {
            float4 v = make_float4((&arow[0].x)[c], (&arow[1].x)[c],
                                   (&arow[2].x)[c], (&arow[3].x)[c]);
            *(float4*)(Tc + (4 * bb + c) * S_ + 4 * a) = v;
        }
        #pragma unroll
        for (int r4 = 0; r4 < 4; r4++)
            #pragma unroll
            for (int c = 0; c < 4; c++)
                P[r4][c] = (&arow[r4].x)[c] +
                           ((4 * a + r4) == (4 * bb + c) ? 1.0f : 0.0f);
    }
    __syncwarp();

    #pragma unroll 1
    for (int n = 2; n <= NTAY; n++) {
        float acc[4][4];
        if (act) {
            #pragma unroll
            for (int r4 = 0; r4 < 4; r4++)
                #pragma unroll
                for (int c = 0; c < 4; c++) acc[r4][c] = 0.0f;
            #pragma unroll
            for (int t = 0; t < S_; t++) {
                const float4 tv = *(const float4*)(Tc + t * S_ + 4 * a);
                const float4 av = *(const float4*)(Arm + t * S_ + 4 * bb);
                const float* tvp = &tv.x;
                const float* avp = &av.x;
                #pragma unroll
                for (int r4 = 0; r4 < 4; r4++)
                    #pragma unroll
                    for (int c = 0; c < 4; c++)
                        acc[r4][c] = fmaf(tvp[r4], avp[c], acc[r4][c]);
            }
        }
        __syncwarp();
        if (act) {
            const float inv = 1.0f / (float)n;
            #pragma unroll
            for (int r4 = 0; r4 < 4; r4++)
                #pragma unroll
                for (int c = 0; c < 4; c++) {
                    acc[r4][c] *= inv;
                    P[r4][c] += acc[r4][c];
                }
            #pragma unroll
            for (int c = 0; c < 4; c++) {
                float4 v = make_float4(acc[0][c], acc[1][c], acc[2][c], acc[3][c]);
                *(float4*)(Tc + (4 * bb + c) * S_ + 4 * a) = v;
            }
        }
        __syncwarp();
    }

    #pragma unroll 1
    for (int q = 0; q < SQN; q++) {
        if (act) {
            #pragma unroll
            for (int r4 = 0; r4 < 4; r4++) {
                float4 v = make_float4(P[r4][0], P[r4][1], P[r4][2], P[r4][3]);
                *(float4*)(Arm + (4 * a + r4) * S_ + 4 * bb) = v;
            }
            #pragma unroll
            for (int c = 0; c < 4; c++) {
                float4 v = make_float4(P[0][c], P[1][c], P[2][c], P[3][c]);
                *(float4*)(Tc + (4 * bb + c) * S_ + 4 * a) = v;
            }
        }
        __syncwarp();
        if (act) {
            float acc[4][4];
            #pragma unroll
            for (int r4 = 0; r4 < 4; r4++)
                #pragma unroll
                for (int c = 0; c < 4; c++) acc[r4][c] = 0.0f;
            #pragma unroll
            for (int t = 0; t < S_; t++) {
                const float4 tv = *(const float4*)(Tc + t * S_ + 4 * a);
                const float4 av = *(const float4*)(Arm + t * S_ + 4 * bb);
                const float* tvp = &tv.x;
                const float* avp = &av.x;
                #pragma unroll
                for (int r4 = 0; r4 < 4; r4++)
                    #pragma unroll
                    for (int c = 0; c < 4; c++)
                        acc[r4][c] = fmaf(tvp[r4], avp[c], acc[r4][c]);
            }
            #pragma unroll
            for (int r4 = 0; r4 < 4; r4++)
                #pragma unroll
                for (int c = 0; c < 4; c++) P[r4][c] = acc[r4][c];
        }
        __syncwarp();
    }

    if (act) {
        #pragma unroll
        for (int r4 = 0; r4 < 4; r4++)
            #pragma unroll
            for (int c = 0; c < 4; c++)
                RT[(4 * a + r4) * ROWW + k * EXT_ + 4 * bb + c] = P[r4][c];
    }
}

// store rows of batch b whose predicate matches (want_ge: c>=S_ or c<S_)
__device__ __forceinline__ void store_pred(
        const int* __restrict__ inputs, float* __restrict__ out,
        const float* __restrict__ RT, int b, int start, int stride, bool want_ge) {
    const int* crow = inputs + (size_t)b * L_;
    const float4* RT4 = (const float4*)RT;
    float4* ob = (float4*)out + (size_t)b * L_ * 52;
    for (int idx = start; idx < L_ * 52; idx += stride) {
        const int p = idx / 52;
        const int j = idx - p * 52;
        const int c = __ldg(crow + p);
        if ((c >= S_) == want_ge)
            __stcs(ob + idx, RT4[c * 52 + j]);
    }
}

__device__ __forceinline__ void store_all(
        const int* __restrict__ inputs, float* __restrict__ out,
        const float* __restrict__ RT, int b, int start, int stride) {
    const int* crow = inputs + (size_t)b * L_;
    const float4* RT4 = (const float4*)RT;
    float4* ob = (float4*)out + (size_t)b * L_ * 52;
    for (int idx = start; idx < L_ * 52; idx += stride) {
        const int p = idx / 52;
        const int j = idx - p * 52;
        const int c = __ldg(crow + p);
        __stcs(ob + idx, RT4[c * 52 + j]);
    }
}

// ---------------------------------------------------------------------------
// Pipelined fused kernel: block handles b0, b0+1.
//  S0: fill const region of both RT buffers.
//  S1: producers expm b0 -> RT0 || consumers store b0 rows with c>=20.
//  S2: producers expm b1 -> RT1 || consumers store b0 rows with c<20.
//  S3: all warps store b1.
// ---------------------------------------------------------------------------
__global__ void __launch_bounds__(NTHR)
fused2_kernel(const int* __restrict__ inputs,
              const int* __restrict__ rate_indices,
              const float* __restrict__ tau_kernel,
              float* __restrict__ out) {
    extern __shared__ __align__(16) float dyn[];
    float* RT0 = dyn;
    float* RT1 = dyn + RTN;
    float* sA  = dyn + 2 * RTN;           // [K_][400]
    float* sT  = sA + K_ * MSZ;           // [K_][400]

    const int tid  = threadIdx.x;
    const int w    = tid >> 5;
    const int lane = tid & 31;
    const int b0   = blockIdx.x * BPB;

    // S0: constant region (one-hot rows + zero pads) into both buffers
    for (int idx = tid; idx < RTN; idx += NTHR) {
        const int c = idx / ROWW;
        const int f = idx - c * ROWW;
        const int kk = f / EXT_;
        const int e  = f - kk * EXT_;
        if (c < S_ && e < S_) continue;
        const float v = (c >= S_ && e == c) ? 1.0f : 0.0f;
        RT0[idx] = v;
        RT1[idx] = v;
    }
    __syncthreads();

    // S1
    if (w < K_) {
        const int   r     = __ldg(rate_indices + b0);
        const float scale = softplus_f(__ldg(tau_kernel + r)) * (1.0f / 64.0f);
        expm_into_rt(RT0, sA + w * MSZ, sT + w * MSZ, w, lane, scale);
    } else {
        store_pred(inputs, out, RT0, b0, tid - 256, NTHR - 256, true);
    }
    __syncthreads();

    // S2
    if (w < K_) {
        const int   r     = __ldg(rate_indices + b0 + 1);
        const float scale = softplus_f(__ldg(tau_kernel + r)) * (1.0f / 64.0f);
        expm_into_rt(RT1, sA + w * MSZ, sT + w * MSZ, w, lane, scale);
    } else {
        store_pred(inputs, out, RT0, b0, tid - 256, NTHR - 256, false);
    }
    __syncthreads();

    // S3: everyone stores b1
    store_all(inputs, out, RT1, b0 + 1, tid, NTHR);
}

// ---------------------------------------------------------------------------
extern "C" void kernel_launch(void* const* d_in, const int* in_sizes, int n_in,
                              void* d_out, int out_size) {
    const int*   inputs       = (const int*)  d_in[0];
    const int*   rate_indices = (const int*)  d_in[1];
    const float* tau_kernel   = (const float*)d_in[2];
    const float* exch         = (const float*)d_in[3];
    const float* freq         = (const float*)d_in[4];
    float*       out          = (float*)d_out;

    (void)in_sizes; (void)n_in; (void)out_size;

    const int smem_bytes = (2 * RTN + 2 * K_ * MSZ) * (int)sizeof(float); // 68864
    cudaFuncSetAttribute(fused2_kernel,
                         cudaFuncAttributeMaxDynamicSharedMemorySize, smem_bytes);

    dim3 tb(S_, S_);
    qprep_kernel<<<K_, tb>>>(exch, freq);
    fused2_kernel<<<B_ / BPB, NTHR, smem_bytes>>>(inputs, rate_indices,
                                                  tau_kernel, out);
}

// round 7
// speedup vs baseline: 1.3019x; 1.3019x over previous
#include <cuda_runtime.h>
#include <cstdint>

#define B_   512
#define L_   1024
#define K_   8
#define NR_  512
#define S_   20
#define EXT_ 26
#define SQN  6
#define ROWW (K_ * EXT_)   // 208
#define MSZ  (S_ * S_)     // 400
#define LT   128
#define WTH  416

// Scratch (device globals; no allocation allowed)
__device__ __align__(16) float g_Q[K_ * MSZ];
__device__ __align__(16) float g_P[(size_t)NR_ * K_ * MSZ];
__device__ unsigned int g_used[NR_];

__device__ __forceinline__ float softplus_f(float x) {
    return fmaxf(x, 0.0f) + log1pf(expf(-fabsf(x)));
}

// ---------------------------------------------------------------------------
// Kernel A: build Q[k]
// ---------------------------------------------------------------------------
__global__ void qprep_kernel(const float* __restrict__ exch,
                             const float* __restrict__ freq) {
    const int k = blockIdx.x;
    const int i = threadIdx.y;
    const int j = threadIdx.x;

    __shared__ float Rs[S_][S_ + 1];
    __shared__ float diag[S_];
    __shared__ float fr[S_];

    if (i == 0) fr[j] = freq[j];

    float e1 = exch[(k * S_ + i) * S_ + j];
    float e2 = exch[(k * S_ + j) * S_ + i];
    float r = softplus_f(0.5f * (e1 + e2));
    if (i == j) r = 0.0f;
    __syncthreads();

    float q = r * fr[j];
    Rs[i][j] = q;
    __syncthreads();

    if (j == 0) {
        float d = 0.0f;
        #pragma unroll
        for (int t = 0; t < S_; t++) d += Rs[i][t];
        diag[i] = d;
    }
    __syncthreads();

    float mue = 0.0f;
    #pragma unroll
    for (int t = 0; t < S_; t++) mue += fr[t] * diag[t];
    mue = fmaxf(mue, 1e-16f);

    float val = q - (i == j ? diag[i] : 0.0f);
    g_Q[(k * S_ + i) * S_ + j] = val / mue;
}

__global__ void clear_used_kernel() {
    int r = blockIdx.x * blockDim.x + threadIdx.x;
    if (r < NR_) g_used[r] = 0u;
}
__global__ void mark_used_kernel(const int* __restrict__ rate_indices) {
    int b = blockIdx.x * blockDim.x + threadIdx.x;
    if (b < B_) g_used[rate_indices[b]] = 1u;
}

// ---------------------------------------------------------------------------
// tile helpers: lane owns 4x4 tile at rows 4a.., cols 4bb..
// ---------------------------------------------------------------------------
__device__ __forceinline__ void mm_tile(const float* __restrict__ Lcm,
                                        const float* __restrict__ Rrm,
                                        int a, int bb, float acc[4][4]) {
    #pragma unroll
    for (int r = 0; r < 4; r++)
        #pragma unroll
        for (int c = 0; c < 4; c++) acc[r][c] = 0.0f;
    #pragma unroll
    for (int t = 0; t < S_; t++) {
        const float4 lv = *(const float4*)(Lcm + t * S_ + 4 * a);
        const float4 rv = *(const float4*)(Rrm + t * S_ + 4 * bb);
        const float* lp = &lv.x;
        const float* rp = &rv.x;
        #pragma unroll
        for (int r = 0; r < 4; r++)
            #pragma unroll
            for (int c = 0; c < 4; c++)
                acc[r][c] = fmaf(lp[r], rp[c], acc[r][c]);
    }
}

__device__ __forceinline__ void wr_rm(float* B, const float t[4][4], int a, int bb) {
    #pragma unroll
    for (int r = 0; r < 4; r++) {
        float4 v = make_float4(t[r][0], t[r][1], t[r][2], t[r][3]);
        *(float4*)(B + (4 * a + r) * S_ + 4 * bb) = v;
    }
}
__device__ __forceinline__ void wr_cm(float* B, const float t[4][4], int a, int bb) {
    #pragma unroll
    for (int c = 0; c < 4; c++) {
        float4 v = make_float4(t[0][c], t[1][c], t[2][c], t[3][c]);
        *(float4*)(B + (4 * bb + c) * S_ + 4 * a) = v;
    }
}

// ---------------------------------------------------------------------------
// expm via Paterson-Stockmeyer degree-8 Taylor (same polynomial as before)
// + 6 squarings. 4 + 6 = 10 matmuls. One warp per (r,k) matrix.
// Triggers PDL dependents after storing g_P.
// ---------------------------------------------------------------------------
__global__ void __launch_bounds__(256)
expm_ps_kernel(const float* __restrict__ tau_kernel) {
    const int lane = threadIdx.x & 31;
    const int w    = threadIdx.x >> 5;
    const int m    = blockIdx.x * 8 + w;
    const int r    = m >> 3;
    const int k    = m & 7;

    __shared__ __align__(16) float sb[8][3][MSZ];   // 38.4 KB

    if (g_used[r]) {
        float* B0 = sb[w][0];
        float* B1 = sb[w][1];
        float* B2 = sb[w][2];

        const bool act = (lane < 25);
        const int  a   = lane / 5;
        const int  bb  = lane - a * 5;

        const float scale = softplus_f(__ldg(tau_kernel + r)) * (1.0f / 64.0f);

        float at[4][4], A2t[4][4], acc[4][4], P[4][4];

        if (act) {
            #pragma unroll
            for (int r4 = 0; r4 < 4; r4++) {
                float4 q = *(const float4*)(g_Q + (k * S_ + 4 * a + r4) * S_ + 4 * bb);
                at[r4][0] = q.x * scale; at[r4][1] = q.y * scale;
                at[r4][2] = q.z * scale; at[r4][3] = q.w * scale;
            }
            wr_rm(B0, at, a, bb);    // A row-major
            wr_cm(B1, at, a, bb);    // A col-major
        }
        __syncwarp();
        if (act) mm_tile(B1, B0, a, bb, A2t);        // A2 = A*A
        __syncwarp();
        if (act) wr_cm(B2, A2t, a, bb);              // A2 col-major
        __syncwarp();
        if (act) mm_tile(B2, B0, a, bb, acc);        // A3 = A2*A
        __syncwarp();                                // readers of B1,B2 done
        if (act) {
            wr_cm(B1, acc, a, bb);                   // A3 col-major
            // q2 = I/720 + A/5040 + A2/40320
            float q[4][4];
            #pragma unroll
            for (int r4 = 0; r4 < 4; r4++)
                #pragma unroll
                for (int c = 0; c < 4; c++)
                    q[r4][c] = ((4 * a + r4) == (4 * bb + c) ? (1.0f / 720.0f) : 0.0f)
                             + at[r4][c] * (1.0f / 5040.0f)
                             + A2t[r4][c] * (1.0f / 40320.0f);
            wr_rm(B2, q, a, bb);
        }
        __syncwarp();
        if (act) mm_tile(B1, B2, a, bb, acc);        // M = A3*q2
        __syncwarp();                                // readers of B2 done
        if (act) {
            // N = q1 + M,  q1 = I/6 + A/24 + A2/120
            float q[4][4];
            #pragma unroll
            for (int r4 = 0; r4 < 4; r4++)
                #pragma unroll
                for (int c = 0; c < 4; c++)
                    q[r4][c] = ((4 * a + r4) == (4 * bb + c) ? (1.0f / 6.0f) : 0.0f)
                             + at[r4][c] * (1.0f / 24.0f)
                             + A2t[r4][c] * (1.0f / 120.0f)
                             + acc[r4][c];
            wr_rm(B2, q, a, bb);
        }
        __syncwarp();
        if (act) {
            mm_tile(B1, B2, a, bb, acc);             // A3*N
            // P = q0 + A3*N,  q0 = I + A + A2/2
            #pragma unroll
            for (int r4 = 0; r4 < 4; r4++)
                #pragma unroll
                for (int c = 0; c < 4; c++)
                    P[r4][c] = ((4 * a + r4) == (4 * bb + c) ? 1.0f : 0.0f)
                             + at[r4][c]
                             + A2t[r4][c] * 0.5f
                             + acc[r4][c];
        }

        // 6 squarings
        #pragma unroll 1
        for (int q = 0; q < SQN; q++) {
            __syncwarp();
            if (act) { wr_rm(B0, P, a, bb); wr_cm(B1, P, a, bb); }
            __syncwarp();
            if (act) {
                mm_tile(B1, B0, a, bb, acc);
                #pragma unroll
                for (int r4 = 0; r4 < 4; r4++)
                    #pragma unroll
                    for (int c = 0; c < 4; c++) P[r4][c] = acc[r4][c];
            }
        }

        if (act) {
            float* dst = g_P + (size_t)m * MSZ;
            #pragma unroll
            for (int r4 = 0; r4 < 4; r4++) {
                float4 v = make_float4(P[r4][0], P[r4][1], P[r4][2], P[r4][3]);
                *(float4*)(dst + (4 * a + r4) * S_ + 4 * bb) = v;
            }
        }
    }

    // PDL: make g_P visible, then signal dependents (per-thread; exits count too)
    __threadfence();
    asm volatile("griddepcontrol.launch_dependents;" ::: "memory");
}

// ---------------------------------------------------------------------------
// Writer with PDL: phase 1 stores one-hot positions (c>=20, no g_P needed)
// while expm runs; griddepcontrol.wait; build RT from g_P; phase 2 stores
// the c<20 positions from RT.
// ---------------------------------------------------------------------------
__global__ void __launch_bounds__(WTH)
writer_pdl_kernel(const int* __restrict__ inputs,
                  const int* __restrict__ rate_indices,
                  float* __restrict__ out) {
    const int b   = blockIdx.y;
    const int l0  = blockIdx.x * LT;
    const int tid = threadIdx.x;

    __shared__ __align__(16) float RT[S_ * ROWW];   // only c<20 rows needed
    __shared__ int cs[LT];

    for (int t = tid; t < LT; t += WTH)
        cs[t] = inputs[b * L_ + l0 + t];
    __syncthreads();

    const int j  = tid % 52;
    const int p0 = tid / 52;                        // 0..7
    float4* ob = (float4*)out + ((size_t)b * L_ + l0) * 52;

    // phase 1: one-hot rows (c >= 20), independent of expm
    {
        const int f0 = 4 * j;
        const int kk = f0 / EXT_;
        const int e0 = f0 - kk * EXT_;              // e of the 4 elements: e0..e0+3 (may wrap)
        int e[4];
        #pragma unroll
        for (int u = 0; u < 4; u++) {
            int f = f0 + u;
            int kx = f / EXT_;
            e[u] = f - kx * EXT_;
        }
        (void)e0;
        #pragma unroll 4
        for (int p = p0; p < LT; p += 8) {
            const int c = cs[p];
            if (c >= S_) {
                float4 v;
                v.x = (e[0] == c) ? 1.0f : 0.0f;
                v.y = (e[1] == c) ? 1.0f : 0.0f;
                v.z = (e[2] == c) ? 1.0f : 0.0f;
                v.w = (e[3] == c) ? 1.0f : 0.0f;
                __stcs(ob + (size_t)p * 52 + j, v);
            }
        }
    }

    // wait for expm's g_P
    asm volatile("griddepcontrol.wait;" ::: "memory");

    // build RT rows c<20 from g_P
    const int r = rate_indices[b];
    const float* Pr = g_P + (size_t)(r * K_) * MSZ;
    for (int idx = tid; idx < S_ * ROWW; idx += WTH) {
        const int c = idx / ROWW;
        const int f = idx - c * ROWW;
        const int kk = f / EXT_;
        const int e  = f - kk * EXT_;
        RT[idx] = (e < S_) ? Pr[kk * MSZ + c * S_ + e] : 0.0f;
    }
    __syncthreads();

    // phase 2: c<20 positions from RT
    const float4* RT4 = (const float4*)RT;
    #pragma unroll 4
    for (int p = p0; p < LT; p += 8) {
        const int c = cs[p];
        if (c < S_)
            __stcs(ob + (size_t)p * 52 + j, RT4[c * 52 + j]);
    }
}

// ---------------------------------------------------------------------------
extern "C" void kernel_launch(void* const* d_in, const int* in_sizes, int n_in,
                              void* d_out, int out_size) {
    const int*   inputs       = (const int*)  d_in[0];
    const int*   rate_indices = (const int*)  d_in[1];
    const float* tau_kernel   = (const float*)d_in[2];
    const float* exch         = (const float*)d_in[3];
    const float* freq         = (const float*)d_in[4];
    float*       out          = (float*)d_out;

    (void)in_sizes; (void)n_in; (void)out_size;

    dim3 tb(S_, S_);
    qprep_kernel<<<K_, tb>>>(exch, freq);
    clear_used_kernel<<<(NR_ + 255) / 256, 256>>>();
    mark_used_kernel<<<(B_ + 255) / 256, 256>>>(rate_indices);
    expm_ps_kernel<<<NR_ * K_ / 8, 256>>>(tau_kernel);

    // writer with programmatic dependent launch (overlap phase-1 with expm)
    cudaLaunchConfig_t cfg = {};
    cfg.gridDim  = dim3(L_ / LT, B_, 1);
    cfg.blockDim = dim3(WTH, 1, 1);
    cfg.dynamicSmemBytes = 0;
    cfg.stream = 0;
    cudaLaunchAttribute attrs[1];
    attrs[0].id = cudaLaunchAttributeProgrammaticStreamSerialization;
    attrs[0].val.programmaticStreamSerializationAllowed = 1;
    cfg.attrs = attrs;
    cfg.numAttrs = 1;

    cudaError_t st = cudaLaunchKernelEx(&cfg, writer_pdl_kernel,
                                        inputs, rate_indices, out);
    if (st != cudaSuccess) {
        // fallback: plain serialized launch (griddepcontrol.wait is a no-op)
        dim3 grid(L_ / LT, B_);
        writer_pdl_kernel<<<grid, WTH>>>(inputs, rate_indices, out);
    }
}